// round 9
// baseline (speedup 1.0000x reference)
#include <cuda_runtime.h>
#include <cuda_bf16.h>

#define B_ 128
#define L_ 1024
#define V_ 30000
#define D_ 256
#define T_ 64

// Scratch (static device globals: allowed; no allocations anywhere)
__device__ float g_P[V_ * T_];      // embed @ W + b   (7.68 MB)
__device__ float g_logz[B_];
__device__ float g_score[B_];

// ---- packed f32x2 helpers (sm_103a FFMA2; PTX-only per SASS_QUICKREF) ----
__device__ __forceinline__ unsigned long long ffma2(unsigned long long a,
                                                    unsigned long long b,
                                                    unsigned long long c) {
    unsigned long long d;
    asm("fma.rn.f32x2 %0, %1, %2, %3;" : "=l"(d) : "l"(a), "l"(b), "l"(c));
    return d;
}
__device__ __forceinline__ unsigned long long pack2(float lo, float hi) {
    unsigned long long d;
    asm("mov.b64 %0, {%1, %2};" : "=l"(d) : "f"(lo), "f"(hi));
    return d;
}
__device__ __forceinline__ float2 unpack2(unsigned long long v) {
    float lo, hi;
    asm("mov.b64 {%0, %1}, %2;" : "=f"(lo), "=f"(hi) : "l"(v));
    return make_float2(lo, hi);
}

// ---------------------------------------------------------------------------
// Kernel 1: P[v][j] = sum_d embed[v][d]*W[d][j] + b[j]
// (round-8 version, measured 55.5us: 4x4 tile/thread, 128 threads/block)
// ---------------------------------------------------------------------------
__global__ void __launch_bounds__(128) proj_kernel(const float* __restrict__ embed,
                                                   const float* __restrict__ W,
                                                   const float* __restrict__ bias) {
    int tid = threadIdx.x;
    int j4  = tid & 15;           // columns j4*4 .. j4*4+3
    int r4  = tid >> 4;           // row group (4 rows each), 0..7
    int vbase = blockIdx.x * 32 + r4 * 4;

    int v0 = min(vbase + 0, V_ - 1);
    int v1 = min(vbase + 1, V_ - 1);
    int v2 = min(vbase + 2, V_ - 1);
    int v3 = min(vbase + 3, V_ - 1);

    const float4* Wv = reinterpret_cast<const float4*>(W);   // [D_][16] float4
    const float4* E0 = reinterpret_cast<const float4*>(embed + (size_t)v0 * D_);
    const float4* E1 = reinterpret_cast<const float4*>(embed + (size_t)v1 * D_);
    const float4* E2 = reinterpret_cast<const float4*>(embed + (size_t)v2 * D_);
    const float4* E3 = reinterpret_cast<const float4*>(embed + (size_t)v3 * D_);

    float4 bb = reinterpret_cast<const float4*>(bias)[j4];
    float4 a0 = bb, a1 = bb, a2 = bb, a3 = bb;

    #pragma unroll 2
    for (int d4 = 0; d4 < D_ / 4; d4++) {
        float4 w0 = Wv[(d4 * 4 + 0) * 16 + j4];
        float4 w1 = Wv[(d4 * 4 + 1) * 16 + j4];
        float4 w2 = Wv[(d4 * 4 + 2) * 16 + j4];
        float4 w3 = Wv[(d4 * 4 + 3) * 16 + j4];
        float4 e0 = E0[d4], e1 = E1[d4], e2 = E2[d4], e3 = E3[d4];

        a0.x = fmaf(e0.x, w0.x, a0.x); a0.y = fmaf(e0.x, w0.y, a0.y);
        a0.z = fmaf(e0.x, w0.z, a0.z); a0.w = fmaf(e0.x, w0.w, a0.w);
        a0.x = fmaf(e0.y, w1.x, a0.x); a0.y = fmaf(e0.y, w1.y, a0.y);
        a0.z = fmaf(e0.y, w1.z, a0.z); a0.w = fmaf(e0.y, w1.w, a0.w);
        a0.x = fmaf(e0.z, w2.x, a0.x); a0.y = fmaf(e0.z, w2.y, a0.y);
        a0.z = fmaf(e0.z, w2.z, a0.z); a0.w = fmaf(e0.z, w2.w, a0.w);
        a0.x = fmaf(e0.w, w3.x, a0.x); a0.y = fmaf(e0.w, w3.y, a0.y);
        a0.z = fmaf(e0.w, w3.z, a0.z); a0.w = fmaf(e0.w, w3.w, a0.w);

        a1.x = fmaf(e1.x, w0.x, a1.x); a1.y = fmaf(e1.x, w0.y, a1.y);
        a1.z = fmaf(e1.x, w0.z, a1.z); a1.w = fmaf(e1.x, w0.w, a1.w);
        a1.x = fmaf(e1.y, w1.x, a1.x); a1.y = fmaf(e1.y, w1.y, a1.y);
        a1.z = fmaf(e1.y, w1.z, a1.z); a1.w = fmaf(e1.y, w1.w, a1.w);
        a1.x = fmaf(e1.z, w2.x, a1.x); a1.y = fmaf(e1.z, w2.y, a1.y);
        a1.z = fmaf(e1.z, w2.z, a1.z); a1.w = fmaf(e1.z, w2.w, a1.w);
        a1.x = fmaf(e1.w, w3.x, a1.x); a1.y = fmaf(e1.w, w3.y, a1.y);
        a1.z = fmaf(e1.w, w3.z, a1.z); a1.w = fmaf(e1.w, w3.w, a1.w);

        a2.x = fmaf(e2.x, w0.x, a2.x); a2.y = fmaf(e2.x, w0.y, a2.y);
        a2.z = fmaf(e2.x, w0.z, a2.z); a2.w = fmaf(e2.x, w0.w, a2.w);
        a2.x = fmaf(e2.y, w1.x, a2.x); a2.y = fmaf(e2.y, w1.y, a2.y);
        a2.z = fmaf(e2.y, w1.z, a2.z); a2.w = fmaf(e2.y, w1.w, a2.w);
        a2.x = fmaf(e2.z, w2.x, a2.x); a2.y = fmaf(e2.z, w2.y, a2.y);
        a2.z = fmaf(e2.z, w2.z, a2.z); a2.w = fmaf(e2.z, w2.w, a2.w);
        a2.x = fmaf(e2.w, w3.x, a2.x); a2.y = fmaf(e2.w, w3.y, a2.y);
        a2.z = fmaf(e2.w, w3.z, a2.z); a2.w = fmaf(e2.w, w3.w, a2.w);

        a3.x = fmaf(e3.x, w0.x, a3.x); a3.y = fmaf(e3.x, w0.y, a3.y);
        a3.z = fmaf(e3.x, w0.z, a3.z); a3.w = fmaf(e3.x, w0.w, a3.w);
        a3.x = fmaf(e3.y, w1.x, a3.x); a3.y = fmaf(e3.y, w1.y, a3.y);
        a3.z = fmaf(e3.y, w1.z, a3.z); a3.w = fmaf(e3.y, w1.w, a3.w);
        a3.x = fmaf(e3.z, w2.x, a3.x); a3.y = fmaf(e3.z, w2.y, a3.y);
        a3.z = fmaf(e3.z, w2.z, a3.z); a3.w = fmaf(e3.z, w2.w, a3.w);
        a3.x = fmaf(e3.w, w3.x, a3.x); a3.y = fmaf(e3.w, w3.y, a3.y);
        a3.z = fmaf(e3.w, w3.z, a3.z); a3.w = fmaf(e3.w, w3.w, a3.w);
    }

    float4* Pv = reinterpret_cast<float4*>(g_P);
    if (vbase + 0 < V_) Pv[(size_t)(vbase + 0) * 16 + j4] = a0;
    if (vbase + 1 < V_) Pv[(size_t)(vbase + 1) * 16 + j4] = a1;
    if (vbase + 2 < V_) Pv[(size_t)(vbase + 2) * 16 + j4] = a2;
    if (vbase + 3 < V_) Pv[(size_t)(vbase + 3) * 16 + j4] = a3;
}

// ---------------------------------------------------------------------------
// Kernel 2: SINGLE-WARP-PER-ROW CRF, smem q-exchange, packed FFMA2 mat-vec.
// Lane owns columns j0=lane, j1=lane+32. exp(trans) held as 64 packed f32x2
// registers. Per step: 16 LDS.128 (q as ulonglong2) + 64 FFMA2 (4 packed
// accumulators) + 2 STS + __syncwarp. NO block barrier, NO shuffles in loop.
// Rescale every 8 steps: local redundant max (identical across lanes),
// power-of-2 factor, ALU only.
// ---------------------------------------------------------------------------
__global__ void __launch_bounds__(32) crf_kernel(const int* __restrict__ x,
                                                 const int* __restrict__ tags,
                                                 const float* __restrict__ trans) {
    int lane = threadIdx.x;
    int row  = blockIdx.x;
    int j0 = lane, j1 = lane + 32;

    __shared__ int stoks[L_];
    __shared__ __align__(16) float pbuf[2][T_];
    __shared__ float strans[T_ * T_];

    const int* xrow = x + (size_t)row * L_;
    const int* trow = tags + (size_t)row * L_;

    for (int i = lane; i < L_; i += 32) stoks[i] = xrow[i];
    for (int i = lane; i < T_ * T_; i += 32) strans[i] = trans[i];
    __syncwarp();

    // exp(trans) column slices, packed in pairs over i:
    // E0[m] = (exp(trans[2m][j0]), exp(trans[2m+1][j0])), E1 for j1
    unsigned long long E0[32], E1[32];
    #pragma unroll
    for (int m = 0; m < 32; m++) {
        E0[m] = pack2(__expf(strans[(2 * m) * T_ + j0]),
                      __expf(strans[(2 * m + 1) * T_ + j0]));
        E1[m] = pack2(__expf(strans[(2 * m) * T_ + j1]),
                      __expf(strans[(2 * m + 1) * T_ + j1]));
    }

    // ---- gold path score (warp-strided) ----
    float sc = 0.f;
    #pragma unroll 4
    for (int pos = lane; pos < L_; pos += 32) {
        int tg = trow[pos];
        sc += __ldg(&g_P[(size_t)stoks[pos] * T_ + tg]);
        if (pos + 1 < L_) sc += strans[tg * T_ + trow[pos + 1]];
    }
    #pragma unroll
    for (int o = 16; o; o >>= 1) sc += __shfl_xor_sync(0xffffffffu, sc, o);
    if (lane == 0) {
        sc += strans[trow[0]];                 // START(0) -> tag0
        sc += strans[trow[L_ - 1] * T_ + 1];   // tag_last -> END(1)
        g_score[row] = sc;
    }

    // ---- init alpha0 (exp-domain); -1e4 entries underflow to exact 0 ----
    pbuf[0][j0] = __expf(strans[j0] + __ldg(&g_P[(size_t)stoks[0] * T_ + j0]));
    pbuf[0][j1] = __expf(strans[j1] + __ldg(&g_P[(size_t)stoks[0] * T_ + j1]));
    float ee0 = __expf(__ldg(&g_P[(size_t)stoks[1] * T_ + j0]));   // exp(e_1)
    float ee1 = __expf(__ldg(&g_P[(size_t)stoks[1] * T_ + j1]));
    float ra0 = __ldg(&g_P[(size_t)stoks[2] * T_ + j0]);           // raw e_2
    float ra1 = __ldg(&g_P[(size_t)stoks[2] * T_ + j1]);
    float logscale = 0.f;
    __syncwarp();

    for (int t = 1; t < L_; t++) {
        // prefetch raw emission for t+2
        int pf = (t + 2 < L_) ? stoks[t + 2] : stoks[L_ - 1];
        size_t tk = (size_t)pf * T_;
        float ra20 = __ldg(&g_P[tk + j0]);
        float ra21 = __ldg(&g_P[tk + j1]);

        const float* pc = pbuf[(t - 1) & 1];
        const ulonglong2* qc = reinterpret_cast<const ulonglong2*>(pc);

        float r = 1.f;
        if ((t & 7) == 0) {
            // 1-in-8 steps: redundant local max (identical across lanes)
            const float4* qf = reinterpret_cast<const float4*>(pc);
            float4 m4 = qf[0];
            #pragma unroll
            for (int k = 1; k < 16; k++) {
                float4 v = qf[k];
                m4.x = fmaxf(m4.x, v.x); m4.y = fmaxf(m4.y, v.y);
                m4.z = fmaxf(m4.z, v.z); m4.w = fmaxf(m4.w, v.w);
            }
            float m = fmaxf(fmaxf(m4.x, m4.y), fmaxf(m4.z, m4.w));
            int eb = (__float_as_int(m) >> 23) & 0xff;
            r = __int_as_float((254 - eb) << 23);          // ~1/m (power of 2)
            logscale += (float)(eb - 127) * 0.6931471805599453f;
        }

        // packed mat-vec: q'[j] = sum_i q[i] * exp(trans[i][j])
        unsigned long long acc0 = 0ull, acc1 = 0ull, acc2 = 0ull, acc3 = 0ull;
        #pragma unroll
        for (int k = 0; k < 16; k++) {
            ulonglong2 v = qc[k];          // q[4k..4k+1] | q[4k+2..4k+3] packed
            acc0 = ffma2(v.x, E0[2 * k], acc0);
            acc1 = ffma2(v.x, E1[2 * k], acc1);
            acc2 = ffma2(v.y, E0[2 * k + 1], acc2);
            acc3 = ffma2(v.y, E1[2 * k + 1], acc3);
        }
        float2 s0 = unpack2(acc0), s2 = unpack2(acc2);
        float2 s1 = unpack2(acc1), s3 = unpack2(acc3);
        float q0 = (s0.x + s0.y) + (s2.x + s2.y);
        float q1 = (s1.x + s1.y) + (s3.x + s3.y);

        pbuf[t & 1][j0] = q0 * (r * ee0);
        pbuf[t & 1][j1] = q1 * (r * ee1);

        ee0 = __expf(ra0); ee1 = __expf(ra1);   // exp for next step, off path
        ra0 = ra20;        ra1 = ra21;
        __syncwarp();
    }

    // ---- log partition ----
    float v = pbuf[(L_ - 1) & 1][j0] * __expf(strans[j0 * T_ + 1])
            + pbuf[(L_ - 1) & 1][j1] * __expf(strans[j1 * T_ + 1]);
    #pragma unroll
    for (int o = 16; o; o >>= 1) v += __shfl_xor_sync(0xffffffffu, v, o);
    if (lane == 0) g_logz[row] = __logf(v) + logscale;
}

// ---------------------------------------------------------------------------
// Kernel 3: out = sum_b (logz - score)
// ---------------------------------------------------------------------------
__global__ void __launch_bounds__(128) reduce_kernel(float* __restrict__ out) {
    int tid = threadIdx.x;
    __shared__ float r[4];
    float v = g_logz[tid] - g_score[tid];
    #pragma unroll
    for (int o = 16; o; o >>= 1) v += __shfl_down_sync(0xffffffffu, v, o);
    if ((tid & 31) == 0) r[tid >> 5] = v;
    __syncthreads();
    if (tid == 0) out[0] = r[0] + r[1] + r[2] + r[3];
}

// ---------------------------------------------------------------------------
// metadata order: x(int), tags(int), mask(f32, unused), embed(f32), W(f32),
//                 b(f32), trans(f32)  -> out: scalar f32
// ---------------------------------------------------------------------------
extern "C" void kernel_launch(void* const* d_in, const int* in_sizes, int n_in,
                              void* d_out, int out_size) {
    const int*   x     = (const int*)d_in[0];
    const int*   tags  = (const int*)d_in[1];
    const float* embed = (const float*)d_in[3];
    const float* W     = (const float*)d_in[4];
    const float* bias  = (const float*)d_in[5];
    const float* trans = (const float*)d_in[6];
    float* out = (float*)d_out;

    proj_kernel<<<(V_ + 31) / 32, 128>>>(embed, W, bias);
    crf_kernel<<<B_, 32>>>(x, tags, trans);
    reduce_kernel<<<1, 128>>>(out);
}